// round 3
// baseline (speedup 1.0000x reference)
#include <cuda_runtime.h>
#include <cstdint>

// ParallelTransport: out[b,i,j,:,:] = 6-term Taylor exp of
//   M[b,i,j] = sum_d (x[b,j,d]-x[b,i,d]) * A[b,j,d,:,:]
//
// R2: packed f32x2 FMA (FFMA2) everywhere.
//   Phase 1: M_tile[256 x 64] = Y[256 x 512] @ A_j[512 x 64], thread tile 8x8,
//            rows packed in f32x2 (X stored transposed), A pre-duplicated (a,a).
//   Phase 2: per-8x8 Taylor, columns packed in f32x2.

#define SS       512
#define DD       512
#define TILE_I   256
#define DK       32
#define THREADS  256
#define XST      260          // floats per Xs row  (260*4 = 1040 = 65*16)
#define AST2     66           // u64 per As2 row    (66*8  = 528, 16B-mult)
#define MST      68           // floats per Ms row  (68*4  = 272 = 17*16)

#define XS_BYTES  (DK * XST * 4)          // 33280
#define AS2_OFF   XS_BYTES
#define AS2_BYTES (DK * AST2 * 8)         // 16896
#define MS_BYTES  (TILE_I * MST * 4)      // 69632
#define DYN_SMEM  (MS_BYTES)              // >= XS_BYTES+AS2_BYTES (50176)

typedef unsigned long long u64;

#define FMA2(D,A,B,C) asm("fma.rn.f32x2 %0,%1,%2,%3;" : "=l"(D) : "l"(A), "l"(B), "l"(C))
#define MUL2(D,A,B)   asm("mul.rn.f32x2 %0,%1,%2;"    : "=l"(D) : "l"(A), "l"(B))
#define ADD2(D,A,B)   asm("add.rn.f32x2 %0,%1,%2;"    : "=l"(D) : "l"(A), "l"(B))

__device__ __forceinline__ u64 pk2(float a, float b) {
    u64 r; asm("mov.b64 %0,{%1,%2};" : "=l"(r) : "f"(a), "f"(b)); return r;
}
__device__ __forceinline__ void upk2(float& a, float& b, u64 v) {
    asm("mov.b64 {%0,%1},%2;" : "=f"(a), "=f"(b) : "l"(v));
}

__global__ __launch_bounds__(THREADS, 2)
void pt_kernel(const float* __restrict__ x,
               const float* __restrict__ A,
               float* __restrict__ out)
{
    extern __shared__ __align__(16) char smraw[];
    float (*Xs)[XST]  = reinterpret_cast<float (*)[XST]>(smraw);
    u64   (*As2)[AST2] = reinterpret_cast<u64 (*)[AST2]>(smraw + AS2_OFF);
    float (*Ms)[MST]  = reinterpret_cast<float (*)[MST]>(smraw);

    const int blk = blockIdx.x;
    const int it  = blk & 1;
    const int j   = (blk >> 1) & (SS - 1);
    const int b   = blk >> 10;
    const int i0  = it * TILE_I;

    const int tid = threadIdx.x;
    const int klg = tid & 7;     // 0..7  -> kl columns klg*8 .. +7
    const int ig  = tid >> 3;    // 0..31 -> rows ig*8 .. +7

    const float* Xb      = x + (size_t)b * SS * DD;
    const float* xi_base = Xb + (size_t)i0 * DD;
    const float* xj      = Xb + (size_t)j * DD;
    const float* Ab      = A + ((size_t)b * SS + j) * DD * 64;

    u64 acc2[4][8];              // row-pair (2*ii2, 2*ii2+1) x col c
#pragma unroll
    for (int ii2 = 0; ii2 < 4; ii2++)
#pragma unroll
        for (int c = 0; c < 8; c++) acc2[ii2][c] = 0ULL;

    for (int dk = 0; dk < DD; dk += DK) {
        // ---- stage A chunk, duplicated (a,a): A[b,j, dk..dk+DK, 0..63]
#pragma unroll
        for (int f = tid; f < DK * 16; f += THREADS) {      // 512 float4 -> 2/thread
            int d = f >> 4, q = f & 15;
            float4 v = *(const float4*)(Ab + (size_t)(dk + d) * 64 + q * 4);
            As2[d][q * 4 + 0] = pk2(v.x, v.x);
            As2[d][q * 4 + 1] = pk2(v.y, v.y);
            As2[d][q * 4 + 2] = pk2(v.z, v.z);
            As2[d][q * 4 + 3] = pk2(v.w, v.w);
        }
        // ---- stage X chunk TRANSPOSED with x_j - x_i applied: Xs[d][row]
#pragma unroll
        for (int f = tid; f < TILE_I * (DK / 4); f += THREADS) {  // 2048 -> 8/thread
            int row = f >> 3, q = f & 7;
            float4 vi = *(const float4*)(xi_base + (size_t)row * DD + dk + q * 4);
            float4 vj = *(const float4*)(xj + dk + q * 4);
            Xs[q * 4 + 0][row] = vj.x - vi.x;
            Xs[q * 4 + 1][row] = vj.y - vi.y;
            Xs[q * 4 + 2][row] = vj.z - vi.z;
            Xs[q * 4 + 3][row] = vj.w - vi.w;
        }
        __syncthreads();

#pragma unroll 2
        for (int d = 0; d < DK; d++) {
            // 8 rows -> 4 packed row-pairs (natural pairs from LDS.128)
            ulonglong2 xA = *(const ulonglong2*)&Xs[d][ig * 8];
            ulonglong2 xB = *(const ulonglong2*)&Xs[d][ig * 8 + 4];
            u64 xp[4] = {xA.x, xA.y, xB.x, xB.y};
            // 8 duplicated A operands (4 x LDS.128)
            ulonglong2 a01 = *(const ulonglong2*)&As2[d][klg * 8 + 0];
            ulonglong2 a23 = *(const ulonglong2*)&As2[d][klg * 8 + 2];
            ulonglong2 a45 = *(const ulonglong2*)&As2[d][klg * 8 + 4];
            ulonglong2 a67 = *(const ulonglong2*)&As2[d][klg * 8 + 6];
            u64 ap[8] = {a01.x, a01.y, a23.x, a23.y, a45.x, a45.y, a67.x, a67.y};
#pragma unroll
            for (int ii2 = 0; ii2 < 4; ii2++)
#pragma unroll
                for (int c = 0; c < 8; c++)
                    FMA2(acc2[ii2][c], xp[ii2], ap[c], acc2[ii2][c]);
        }
        __syncthreads();
    }

    // ---- dump M tile into shared (aliases Xs/As2; loop-final sync covers WAR)
#pragma unroll
    for (int ii2 = 0; ii2 < 4; ii2++) {
        float lo[8], hi[8];
#pragma unroll
        for (int c = 0; c < 8; c++) upk2(lo[c], hi[c], acc2[ii2][c]);
        int r0 = ig * 8 + 2 * ii2;
        *(float4*)&Ms[r0][klg * 8]         = make_float4(lo[0], lo[1], lo[2], lo[3]);
        *(float4*)&Ms[r0][klg * 8 + 4]     = make_float4(lo[4], lo[5], lo[6], lo[7]);
        *(float4*)&Ms[r0 + 1][klg * 8]     = make_float4(hi[0], hi[1], hi[2], hi[3]);
        *(float4*)&Ms[r0 + 1][klg * 8 + 4] = make_float4(hi[4], hi[5], hi[6], hi[7]);
    }
    __syncthreads();

    // ---- Taylor: 8 lanes per 8x8 matrix, one row per lane, 8 passes, f32x2
    const int r     = tid & 7;
    const int mbase = tid >> 3;   // 0..31

    const float invn[7] = {0.f, 1.f, 0.5f, 1.f / 3.f, 0.25f, 0.2f, 1.f / 6.f};

#pragma unroll 1
    for (int p = 0; p < 8; p++) {
        const int m = p * 32 + mbase;

        // full M, rows k, columns packed in pairs
        u64 Mg[8][4];
#pragma unroll
        for (int k = 0; k < 8; k++) {
            ulonglong2 t0 = *(const ulonglong2*)&Ms[m][k * 8];
            ulonglong2 t1 = *(const ulonglong2*)&Ms[m][k * 8 + 4];
            Mg[k][0] = t0.x; Mg[k][1] = t0.y; Mg[k][2] = t1.x; Mg[k][3] = t1.y;
        }
        // own row r: current power P and running result
        u64 P[4], res[4];
        {
            ulonglong2 t0 = *(const ulonglong2*)&Ms[m][r * 8];
            ulonglong2 t1 = *(const ulonglong2*)&Ms[m][r * 8 + 4];
            P[0] = t0.x; P[1] = t0.y; P[2] = t1.x; P[3] = t1.y;
        }
#pragma unroll
        for (int c2 = 0; c2 < 4; c2++) res[c2] = P[c2];

#pragma unroll
        for (int n = 2; n <= 6; n++) {
            float ps[8];
#pragma unroll
            for (int c2 = 0; c2 < 4; c2++) upk2(ps[2 * c2], ps[2 * c2 + 1], P[c2]);
            u64 nw[4] = {0ULL, 0ULL, 0ULL, 0ULL};
#pragma unroll
            for (int k = 0; k < 8; k++) {
                u64 s2 = pk2(ps[k], ps[k]);
#pragma unroll
                for (int c2 = 0; c2 < 4; c2++)
                    FMA2(nw[c2], s2, Mg[k][c2], nw[c2]);
            }
            uint32_t ub = __float_as_uint(invn[n]);
            u64 sc2 = (u64)ub | ((u64)ub << 32);
#pragma unroll
            for (int c2 = 0; c2 < 4; c2++) {
                MUL2(nw[c2], nw[c2], sc2);
                P[c2] = nw[c2];
                ADD2(res[c2], res[c2], nw[c2]);
            }
        }

        float fr[8];
#pragma unroll
        for (int c2 = 0; c2 < 4; c2++) upk2(fr[2 * c2], fr[2 * c2 + 1], res[c2]);
#pragma unroll
        for (int c = 0; c < 8; c++) fr[c] += (c == r) ? 1.0f : 0.0f;   // identity

        size_t off = (((size_t)b * SS + (i0 + m)) * SS + j) * 64 + (size_t)r * 8;
        *(float4*)(out + off)     = make_float4(fr[0], fr[1], fr[2], fr[3]);
        *(float4*)(out + off + 4) = make_float4(fr[4], fr[5], fr[6], fr[7]);
    }
}

extern "C" void kernel_launch(void* const* d_in, const int* in_sizes, int n_in,
                              void* d_out, int out_size)
{
    const float* x = (const float*)d_in[0];   // [4,512,512]
    const float* A = (const float*)d_in[1];   // [4,512,512,8,8]
    float* out = (float*)d_out;               // [4,512,512,8,8]
    (void)in_sizes; (void)n_in; (void)out_size;

    cudaFuncSetAttribute(pt_kernel, cudaFuncAttributeMaxDynamicSharedMemorySize, DYN_SMEM);

    dim3 grid(4 * 512 * 2);   // (b, j, i-tile), i-tile fastest
    dim3 block(THREADS);
    pt_kernel<<<grid, block, DYN_SMEM>>>(x, A, out);
}